// round 1
// baseline (speedup 1.0000x reference)
#include <cuda_runtime.h>
#include <math.h>

#define NNODES 50000
#define FIN    512
#define HDIM   128
#define CDIM   64
#define NEDGE  800000

// ---------------------------------------------------------------------------
// Scratch (no allocations allowed -> __device__ globals)
// ---------------------------------------------------------------------------
__device__ float g_xl[NNODES * HDIM];   // X @ W_low
__device__ float g_xh[NNODES * HDIM];   // X @ W_high
__device__ float g_xm[NNODES * HDIM];   // X @ W_mlp
__device__ float g_sl[NNODES * HDIM];   // adj_low @ xl  (atomic accum)
__device__ float g_sh[NNODES * HDIM];   // adj_low @ xh  (atomic accum)
__device__ float g_h1[NNODES * HDIM];   // layer-1 output
__device__ float g_yl[NNODES * CDIM];
__device__ float g_yh[NNODES * CDIM];
__device__ float g_ym[NNODES * CDIM];
__device__ float g_tl[NNODES * CDIM];
__device__ float g_th[NNODES * CDIM];

// ---------------------------------------------------------------------------
// Utilities
// ---------------------------------------------------------------------------
__device__ __forceinline__ float warpSum(float v) {
    #pragma unroll
    for (int o = 16; o > 0; o >>= 1) v += __shfl_xor_sync(0xFFFFFFFFu, v, o);
    return v;
}
__device__ __forceinline__ float warpMax(float v) {
    #pragma unroll
    for (int o = 16; o > 0; o >>= 1) v = fmaxf(v, __shfl_xor_sync(0xFFFFFFFFu, v, o));
    return v;
}
__device__ __forceinline__ void red_add_v4(float* p, float a, float b, float c, float d) {
    asm volatile("red.global.add.v4.f32 [%0], {%1, %2, %3, %4};"
                 :: "l"(p), "f"(a), "f"(b), "f"(c), "f"(d) : "memory");
}

__global__ void zero4_kernel(float4* p, int n4) {
    int i = blockIdx.x * blockDim.x + threadIdx.x;
    if (i < n4) p[i] = make_float4(0.f, 0.f, 0.f, 0.f);
}

// ---------------------------------------------------------------------------
// Tiled FP32 SGEMM:  C[M,Nn] = A[M,K] @ B[K,Nn]   (all row-major)
// ---------------------------------------------------------------------------
template<int BM, int BN, int BK, int TM, int TN>
__global__ void sgemm_kernel(const float* __restrict__ A,
                             const float* __restrict__ B,
                             float* __restrict__ C,
                             int M, int Nn, int K) {
    constexpr int THREADS = (BM / TM) * (BN / TN);
    __shared__ float As[BK][BM];
    __shared__ float Bs[BK][BN];

    const int tid  = threadIdx.x;
    const int bm   = blockIdx.y * BM;
    const int bn   = blockIdx.x * BN;
    const int tRow = (tid / (BN / TN)) * TM;
    const int tCol = (tid % (BN / TN)) * TN;

    float acc[TM][TN];
    #pragma unroll
    for (int i = 0; i < TM; i++)
        #pragma unroll
        for (int j = 0; j < TN; j++) acc[i][j] = 0.f;

    for (int k0 = 0; k0 < K; k0 += BK) {
        // Load A tile (BM x BK), transposed into As[BK][BM]
        #pragma unroll
        for (int idx = tid * 4; idx < BM * BK; idx += THREADS * 4) {
            int r = idx / BK;
            int c = idx % BK;          // multiple of 4 (BK % 4 == 0)
            int gr = bm + r;
            float4 v = make_float4(0.f, 0.f, 0.f, 0.f);
            if (gr < M)
                v = *reinterpret_cast<const float4*>(&A[(size_t)gr * K + k0 + c]);
            As[c + 0][r] = v.x;
            As[c + 1][r] = v.y;
            As[c + 2][r] = v.z;
            As[c + 3][r] = v.w;
        }
        // Load B tile (BK x BN)
        #pragma unroll
        for (int idx = tid * 4; idx < BK * BN; idx += THREADS * 4) {
            int r = idx / BN;
            int c = idx % BN;
            *reinterpret_cast<float4*>(&Bs[r][c]) =
                *reinterpret_cast<const float4*>(&B[(size_t)(k0 + r) * Nn + bn + c]);
        }
        __syncthreads();

        #pragma unroll
        for (int kk = 0; kk < BK; kk++) {
            float regM[TM], regN[TN];
            #pragma unroll
            for (int i = 0; i < TM; i++) regM[i] = As[kk][tRow + i];
            #pragma unroll
            for (int j = 0; j < TN; j++) regN[j] = Bs[kk][tCol + j];
            #pragma unroll
            for (int i = 0; i < TM; i++)
                #pragma unroll
                for (int j = 0; j < TN; j++)
                    acc[i][j] += regM[i] * regN[j];
        }
        __syncthreads();
    }

    #pragma unroll
    for (int i = 0; i < TM; i++) {
        int gr = bm + tRow + i;
        if (gr < M) {
            #pragma unroll
            for (int j = 0; j < TN; j += 4) {
                float4 v = make_float4(acc[i][j], acc[i][j+1], acc[i][j+2], acc[i][j+3]);
                *reinterpret_cast<float4*>(&C[(size_t)gr * Nn + bn + tCol + j]) = v;
            }
        }
    }
}

// ---------------------------------------------------------------------------
// SpMM layer 1: one warp per edge; s_low[row] += val * xl[col],
//               s_high[row] += val * xh[col]   (128 feats = 32 float4/warp)
// ---------------------------------------------------------------------------
__global__ void spmm1_kernel(const int* __restrict__ erow,
                             const int* __restrict__ ecol,
                             const float* __restrict__ eval) {
    int wid  = (blockIdx.x * blockDim.x + threadIdx.x) >> 5;
    int lane = threadIdx.x & 31;
    if (wid >= NEDGE) return;
    int   r = __ldg(&erow[wid]);
    int   c = __ldg(&ecol[wid]);
    float v = __ldg(&eval[wid]);

    const float4* xl4 = reinterpret_cast<const float4*>(g_xl) + (size_t)c * 32;
    const float4* xh4 = reinterpret_cast<const float4*>(g_xh) + (size_t)c * 32;
    float4 a = __ldg(&xl4[lane]);
    float4 b = __ldg(&xh4[lane]);

    float* sl = g_sl + (size_t)r * HDIM + lane * 4;
    float* sh = g_sh + (size_t)r * HDIM + lane * 4;
    red_add_v4(sl, v * a.x, v * a.y, v * a.z, v * a.w);
    red_add_v4(sh, v * b.x, v * b.y, v * b.z, v * b.w);
}

// ---------------------------------------------------------------------------
// SpMM layer 2: 64 feats; lanes 0-15 -> low path, lanes 16-31 -> high path
// ---------------------------------------------------------------------------
__global__ void spmm2_kernel(const int* __restrict__ erow,
                             const int* __restrict__ ecol,
                             const float* __restrict__ eval) {
    int wid  = (blockIdx.x * blockDim.x + threadIdx.x) >> 5;
    int lane = threadIdx.x & 31;
    if (wid >= NEDGE) return;
    int   r = __ldg(&erow[wid]);
    int   c = __ldg(&ecol[wid]);
    float v = __ldg(&eval[wid]);

    int half = lane >> 4;      // 0: low, 1: high
    int l16  = lane & 15;
    const float* src = half ? g_yh : g_yl;
    float*       dst = half ? g_th : g_tl;

    float4 a = __ldg(reinterpret_cast<const float4*>(src) + (size_t)c * 16 + l16);
    red_add_v4(dst + (size_t)r * CDIM + l16 * 4, v * a.x, v * a.y, v * a.z, v * a.w);
}

// ---------------------------------------------------------------------------
// Attention + combine, layer 1: one warp per node (128 feats = float4/lane)
// ---------------------------------------------------------------------------
__global__ void attn1_kernel(const float* __restrict__ a_low,
                             const float* __restrict__ a_high,
                             const float* __restrict__ a_mlp,
                             const float* __restrict__ av) {
    int wid  = (blockIdx.x * blockDim.x + threadIdx.x) >> 5;
    int lane = threadIdx.x & 31;
    if (wid >= NNODES) return;
    size_t base = (size_t)wid * 32 + lane;

    float4 sl = reinterpret_cast<const float4*>(g_sl)[base];
    float4 xh = reinterpret_cast<const float4*>(g_xh)[base];
    float4 sh = reinterpret_cast<const float4*>(g_sh)[base];
    float4 xm = reinterpret_cast<const float4*>(g_xm)[base];

    float4 ol, oh, om;
    ol.x = fmaxf(sl.x, 0.f); ol.y = fmaxf(sl.y, 0.f); ol.z = fmaxf(sl.z, 0.f); ol.w = fmaxf(sl.w, 0.f);
    oh.x = fmaxf(xh.x - sh.x, 0.f); oh.y = fmaxf(xh.y - sh.y, 0.f);
    oh.z = fmaxf(xh.z - sh.z, 0.f); oh.w = fmaxf(xh.w - sh.w, 0.f);
    om.x = fmaxf(xm.x, 0.f); om.y = fmaxf(xm.y, 0.f); om.z = fmaxf(xm.z, 0.f); om.w = fmaxf(xm.w, 0.f);

    float4 wl = reinterpret_cast<const float4*>(a_low)[lane];
    float4 wh = reinterpret_cast<const float4*>(a_high)[lane];
    float4 wm = reinterpret_cast<const float4*>(a_mlp)[lane];

    float dl = warpSum(ol.x*wl.x + ol.y*wl.y + ol.z*wl.z + ol.w*wl.w);
    float dh = warpSum(oh.x*wh.x + oh.y*wh.y + oh.z*wh.z + oh.w*wh.w);
    float dm = warpSum(om.x*wm.x + om.y*wm.y + om.z*wm.z + om.w*wm.w);

    float s0 = 1.f / (1.f + expf(-dl));
    float s1 = 1.f / (1.f + expf(-dh));
    float s2 = 1.f / (1.f + expf(-dm));

    const float invT = 1.f / 3.f;
    float l0 = (s0*av[0] + s1*av[3] + s2*av[6]) * invT;
    float l1 = (s0*av[1] + s1*av[4] + s2*av[7]) * invT;
    float l2 = (s0*av[2] + s1*av[5] + s2*av[8]) * invT;
    float mx = fmaxf(l0, fmaxf(l1, l2));
    float e0 = expf(l0 - mx), e1 = expf(l1 - mx), e2 = expf(l2 - mx);
    float inv = 3.f / (e0 + e1 + e2);           // fold the *3 scale here
    float al = e0 * inv, ah = e1 * inv, am = e2 * inv;

    float4 o;
    o.x = al*ol.x + ah*oh.x + am*om.x;
    o.y = al*ol.y + ah*oh.y + am*om.y;
    o.z = al*ol.z + ah*oh.z + am*om.z;
    o.w = al*ol.w + ah*oh.w + am*om.w;
    reinterpret_cast<float4*>(g_h1)[base] = o;
}

// ---------------------------------------------------------------------------
// Attention + combine + log_softmax, layer 2: one warp/node (64 = float2/lane)
// ---------------------------------------------------------------------------
__global__ void attn2_kernel(const float* __restrict__ a_low,
                             const float* __restrict__ a_high,
                             const float* __restrict__ a_mlp,
                             const float* __restrict__ av,
                             float* __restrict__ out) {
    int wid  = (blockIdx.x * blockDim.x + threadIdx.x) >> 5;
    int lane = threadIdx.x & 31;
    if (wid >= NNODES) return;
    size_t base = (size_t)wid * 32 + lane;   // float2 index

    float2 tl = reinterpret_cast<const float2*>(g_tl)[base];
    float2 yh = reinterpret_cast<const float2*>(g_yh)[base];
    float2 th = reinterpret_cast<const float2*>(g_th)[base];
    float2 ym = reinterpret_cast<const float2*>(g_ym)[base];

    float2 ol, oh, om;
    ol.x = fmaxf(tl.x, 0.f);        ol.y = fmaxf(tl.y, 0.f);
    oh.x = fmaxf(yh.x - th.x, 0.f); oh.y = fmaxf(yh.y - th.y, 0.f);
    om.x = fmaxf(ym.x, 0.f);        om.y = fmaxf(ym.y, 0.f);

    float2 wl = reinterpret_cast<const float2*>(a_low)[lane];
    float2 wh = reinterpret_cast<const float2*>(a_high)[lane];
    float2 wm = reinterpret_cast<const float2*>(a_mlp)[lane];

    float dl = warpSum(ol.x*wl.x + ol.y*wl.y);
    float dh = warpSum(oh.x*wh.x + oh.y*wh.y);
    float dm = warpSum(om.x*wm.x + om.y*wm.y);

    float s0 = 1.f / (1.f + expf(-dl));
    float s1 = 1.f / (1.f + expf(-dh));
    float s2 = 1.f / (1.f + expf(-dm));

    const float invT = 1.f / 3.f;
    float l0 = (s0*av[0] + s1*av[3] + s2*av[6]) * invT;
    float l1 = (s0*av[1] + s1*av[4] + s2*av[7]) * invT;
    float l2 = (s0*av[2] + s1*av[5] + s2*av[8]) * invT;
    float mx = fmaxf(l0, fmaxf(l1, l2));
    float e0 = expf(l0 - mx), e1 = expf(l1 - mx), e2 = expf(l2 - mx);
    float inv = 3.f / (e0 + e1 + e2);
    float al = e0 * inv, ah = e1 * inv, am = e2 * inv;

    float v0 = al*ol.x + ah*oh.x + am*om.x;
    float v1 = al*ol.y + ah*oh.y + am*om.y;

    // row-wise log_softmax over 64 values (2 per lane)
    float rmax = warpMax(fmaxf(v0, v1));
    float sexp = warpSum(expf(v0 - rmax) + expf(v1 - rmax));
    float lse  = rmax + logf(sexp);

    float2 o = make_float2(v0 - lse, v1 - lse);
    reinterpret_cast<float2*>(out)[base] = o;
}

// ---------------------------------------------------------------------------
// Launch
// ---------------------------------------------------------------------------
extern "C" void kernel_launch(void* const* d_in, const int* in_sizes, int n_in,
                              void* d_out, int out_size) {
    const float* x    = (const float*)d_in[0];
    const int*   erow = (const int*)  d_in[1];
    const int*   ecol = (const int*)  d_in[2];
    const float* eval = (const float*)d_in[3];
    const float* W_l  = (const float*)d_in[4];
    const float* W_h  = (const float*)d_in[5];
    const float* W_m  = (const float*)d_in[6];
    const float* a_l  = (const float*)d_in[7];
    const float* a_h  = (const float*)d_in[8];
    const float* a_m  = (const float*)d_in[9];
    const float* av   = (const float*)d_in[10];
    const float* W_l2 = (const float*)d_in[11];
    const float* W_h2 = (const float*)d_in[12];
    const float* W_m2 = (const float*)d_in[13];
    const float* a_l2 = (const float*)d_in[14];
    const float* a_h2 = (const float*)d_in[15];
    const float* a_m2 = (const float*)d_in[16];
    const float* av2  = (const float*)d_in[17];
    float* out = (float*)d_out;

    float *xl, *xh, *xm, *sl, *sh, *h1, *yl, *yh, *ym, *tl, *th;
    cudaGetSymbolAddress((void**)&xl, g_xl);
    cudaGetSymbolAddress((void**)&xh, g_xh);
    cudaGetSymbolAddress((void**)&xm, g_xm);
    cudaGetSymbolAddress((void**)&sl, g_sl);
    cudaGetSymbolAddress((void**)&sh, g_sh);
    cudaGetSymbolAddress((void**)&h1, g_h1);
    cudaGetSymbolAddress((void**)&yl, g_yl);
    cudaGetSymbolAddress((void**)&yh, g_yh);
    cudaGetSymbolAddress((void**)&ym, g_ym);
    cudaGetSymbolAddress((void**)&tl, g_tl);
    cudaGetSymbolAddress((void**)&th, g_th);

    // Zero the atomic accumulators
    int n4h = NNODES * HDIM / 4;
    int n4c = NNODES * CDIM / 4;
    zero4_kernel<<<(n4h + 255) / 256, 256>>>((float4*)sl, n4h);
    zero4_kernel<<<(n4h + 255) / 256, 256>>>((float4*)sh, n4h);
    zero4_kernel<<<(n4c + 255) / 256, 256>>>((float4*)tl, n4c);
    zero4_kernel<<<(n4c + 255) / 256, 256>>>((float4*)th, n4c);

    // Layer 1 GEMMs: [50000,512] @ [512,128]
    dim3 g1(1, (NNODES + 127) / 128);
    sgemm_kernel<128,128,8,8,8><<<g1, 256>>>(x, W_l, xl, NNODES, HDIM, FIN);
    sgemm_kernel<128,128,8,8,8><<<g1, 256>>>(x, W_h, xh, NNODES, HDIM, FIN);
    sgemm_kernel<128,128,8,8,8><<<g1, 256>>>(x, W_m, xm, NNODES, HDIM, FIN);

    // SpMM + attention
    int eb = (NEDGE * 32 + 255) / 256;
    spmm1_kernel<<<eb, 256>>>(erow, ecol, eval);
    int nb = (NNODES * 32 + 255) / 256;
    attn1_kernel<<<nb, 256>>>(a_l, a_h, a_m, av);

    // Layer 2 GEMMs: [50000,128] @ [128,64]
    dim3 g2(1, (NNODES + 127) / 128);
    sgemm_kernel<128,64,8,8,4><<<g2, 256>>>(h1, W_l2, yl, NNODES, CDIM, HDIM);
    sgemm_kernel<128,64,8,8,4><<<g2, 256>>>(h1, W_h2, yh, NNODES, CDIM, HDIM);
    sgemm_kernel<128,64,8,8,4><<<g2, 256>>>(h1, W_m2, ym, NNODES, CDIM, HDIM);

    spmm2_kernel<<<eb, 256>>>(erow, ecol, eval);
    attn2_kernel<<<nb, 256>>>(a_l2, a_h2, a_m2, av2, out);
}

// round 3
// speedup vs baseline: 1.6026x; 1.6026x over previous
#include <cuda_runtime.h>
#include <math.h>
#include <stdint.h>

#define NNODES 50000
#define FIN    512
#define HDIM   128
#define CDIM   64
#define NEDGE  800000
#define N1     384     // fused layer-1 width: [low | high | mlp] * 128
#define N2     192     // fused layer-2 width: [low | high | mlp] * 64

// ---------------------------------------------------------------------------
// Scratch (no allocations allowed -> __device__ globals)
// ---------------------------------------------------------------------------
__device__ float g_x1[NNODES * N1];     // X @ [W_l|W_h|W_m]
__device__ float g_sl[NNODES * HDIM];   // adj_low @ xl  (atomic accum)
__device__ float g_sh[NNODES * HDIM];   // adj_low @ xh  (atomic accum)
__device__ float g_h1[NNODES * HDIM];   // layer-1 output
__device__ float g_y [NNODES * N2];     // h1 @ [W_l2|W_h2|W_m2]
__device__ float g_tl[NNODES * CDIM];
__device__ float g_th[NNODES * CDIM];
__device__ float g_W1[FIN * N1];        // packed layer-1 weights
__device__ float g_W2[HDIM * N2];       // packed layer-2 weights

// ---------------------------------------------------------------------------
// Utilities
// ---------------------------------------------------------------------------
__device__ __forceinline__ float warpSum(float v) {
    #pragma unroll
    for (int o = 16; o > 0; o >>= 1) v += __shfl_xor_sync(0xFFFFFFFFu, v, o);
    return v;
}
__device__ __forceinline__ float warpMax(float v) {
    #pragma unroll
    for (int o = 16; o > 0; o >>= 1) v = fmaxf(v, __shfl_xor_sync(0xFFFFFFFFu, v, o));
    return v;
}
__device__ __forceinline__ void red_add_v4(float* p, float a, float b, float c, float d) {
    asm volatile("red.global.add.v4.f32 [%0], {%1, %2, %3, %4};"
                 :: "l"(p), "f"(a), "f"(b), "f"(c), "f"(d) : "memory");
}

// tf32 hi/lo split: hi keeps the top 10 mantissa bits (exact tf32), lo = v - hi.
__device__ __forceinline__ void split_tf32(float v, uint32_t& hi, uint32_t& lo) {
    uint32_t h = __float_as_uint(v) & 0xFFFFE000u;
    hi = h;
    lo = __float_as_uint(v - __uint_as_float(h));
}

__device__ __forceinline__ void mma_tf32(float* d, const uint32_t* a, const uint32_t* b) {
    asm volatile(
        "mma.sync.aligned.m16n8k8.row.col.f32.tf32.tf32.f32 "
        "{%0,%1,%2,%3}, {%4,%5,%6,%7}, {%8,%9}, {%0,%1,%2,%3};\n"
        : "+f"(d[0]), "+f"(d[1]), "+f"(d[2]), "+f"(d[3])
        : "r"(a[0]), "r"(a[1]), "r"(a[2]), "r"(a[3]), "r"(b[0]), "r"(b[1]));
}

// ---------------------------------------------------------------------------
// Weight packing
// ---------------------------------------------------------------------------
__global__ void pack_w1_kernel(const float* __restrict__ wl,
                               const float* __restrict__ wh,
                               const float* __restrict__ wm) {
    int i = blockIdx.x * blockDim.x + threadIdx.x;
    if (i >= FIN * HDIM) return;
    int k = i / HDIM, j = i % HDIM;
    g_W1[k * N1 + j]            = wl[i];
    g_W1[k * N1 + HDIM + j]     = wh[i];
    g_W1[k * N1 + 2 * HDIM + j] = wm[i];
}
__global__ void pack_w2_kernel(const float* __restrict__ wl,
                               const float* __restrict__ wh,
                               const float* __restrict__ wm) {
    int i = blockIdx.x * blockDim.x + threadIdx.x;
    if (i >= HDIM * CDIM) return;
    int k = i / CDIM, j = i % CDIM;
    g_W2[k * N2 + j]            = wl[i];
    g_W2[k * N2 + CDIM + j]     = wh[i];
    g_W2[k * N2 + 2 * CDIM + j] = wm[i];
}

// ---------------------------------------------------------------------------
// TF32 3x-split tensor-core GEMM:  C[M,N] = A[M,K] @ B[K,N]  (row-major)
// 256 threads = 8 warps arranged (BM/WM) x (BN/WN); per warp: m16n8k8 mma tiles.
// ---------------------------------------------------------------------------
template<int BM, int BN, int BK, int WM, int WN>
__global__ __launch_bounds__(256)
void gemm3_tf32_kernel(const float* __restrict__ A,
                       const float* __restrict__ B,
                       float* __restrict__ C,
                       int M, int N, int K) {
    constexpr int WARPS_N = BN / WN;
    constexpr int MT = WM / 16;
    constexpr int NT = WN / 8;

    __shared__ float As[BK][BM + 4];   // k-major (transposed) A tile
    __shared__ float Bs[BK][BN + 4];   // k-major B tile

    const int tid  = threadIdx.x;
    const int warp = tid >> 5;
    const int lane = tid & 31;
    const int g    = lane >> 2;   // 0..7
    const int t    = lane & 3;    // 0..3
    const int wmB  = (warp / WARPS_N) * WM;
    const int wnB  = (warp % WARPS_N) * WN;
    const int bm   = blockIdx.y * BM;
    const int bn   = blockIdx.x * BN;

    float acc[MT][NT][4];
    #pragma unroll
    for (int i = 0; i < MT; i++)
        #pragma unroll
        for (int j = 0; j < NT; j++)
            #pragma unroll
            for (int q = 0; q < 4; q++) acc[i][j][q] = 0.f;

    for (int k0 = 0; k0 < K; k0 += BK) {
        // A tile (BM x BK) -> As[k][m], zero-pad rows >= M
        #pragma unroll
        for (int idx = tid * 4; idx < BM * BK; idx += 256 * 4) {
            int r = idx / BK;
            int c = idx % BK;
            int gr = bm + r;
            float4 v = make_float4(0.f, 0.f, 0.f, 0.f);
            if (gr < M)
                v = *reinterpret_cast<const float4*>(&A[(size_t)gr * K + k0 + c]);
            As[c + 0][r] = v.x;
            As[c + 1][r] = v.y;
            As[c + 2][r] = v.z;
            As[c + 3][r] = v.w;
        }
        // B tile (BK x BN) -> Bs[k][n]
        #pragma unroll
        for (int idx = tid * 4; idx < BK * BN; idx += 256 * 4) {
            int r = idx / BN;
            int c = idx % BN;
            *reinterpret_cast<float4*>(&Bs[r][c]) =
                *reinterpret_cast<const float4*>(&B[(size_t)(k0 + r) * N + bn + c]);
        }
        __syncthreads();

        #pragma unroll
        for (int kk = 0; kk < BK; kk += 8) {
            // A fragments (hi/lo) for MT m16-tiles
            uint32_t ah[MT][4], al[MT][4];
            #pragma unroll
            for (int mt = 0; mt < MT; mt++) {
                int mb = wmB + mt * 16;
                split_tf32(As[kk + t]    [mb + g],     ah[mt][0], al[mt][0]);
                split_tf32(As[kk + t]    [mb + g + 8], ah[mt][1], al[mt][1]);
                split_tf32(As[kk + t + 4][mb + g],     ah[mt][2], al[mt][2]);
                split_tf32(As[kk + t + 4][mb + g + 8], ah[mt][3], al[mt][3]);
            }
            #pragma unroll
            for (int nt = 0; nt < NT; nt++) {
                uint32_t bh[2], bl[2];
                int nb = wnB + nt * 8 + g;
                split_tf32(Bs[kk + t]    [nb], bh[0], bl[0]);
                split_tf32(Bs[kk + t + 4][nb], bh[1], bl[1]);
                #pragma unroll
                for (int mt = 0; mt < MT; mt++) {
                    mma_tf32(acc[mt][nt], al[mt], bh);   // lo*hi
                    mma_tf32(acc[mt][nt], ah[mt], bl);   // hi*lo
                    mma_tf32(acc[mt][nt], ah[mt], bh);   // hi*hi
                }
            }
        }
        __syncthreads();
    }

    // Epilogue: c0,c1 = (g, 2t),(g, 2t+1); c2,c3 = (g+8, 2t),(g+8, 2t+1)
    #pragma unroll
    for (int mt = 0; mt < MT; mt++) {
        int r0 = bm + wmB + mt * 16 + g;
        int r1 = r0 + 8;
        #pragma unroll
        for (int nt = 0; nt < NT; nt++) {
            int c0 = bn + wnB + nt * 8 + 2 * t;
            if (r0 < M) {
                float2 v = make_float2(acc[mt][nt][0], acc[mt][nt][1]);
                *reinterpret_cast<float2*>(&C[(size_t)r0 * N + c0]) = v;
            }
            if (r1 < M) {
                float2 v = make_float2(acc[mt][nt][2], acc[mt][nt][3]);
                *reinterpret_cast<float2*>(&C[(size_t)r1 * N + c0]) = v;
            }
        }
    }
}

// ---------------------------------------------------------------------------
// SpMM layer 1: one warp per edge; gathers low+high halves from fused g_x1
// ---------------------------------------------------------------------------
__global__ void spmm1_kernel(const int* __restrict__ erow,
                             const int* __restrict__ ecol,
                             const float* __restrict__ eval) {
    int wid  = (blockIdx.x * blockDim.x + threadIdx.x) >> 5;
    int lane = threadIdx.x & 31;
    if (wid >= NEDGE) return;
    int   r = __ldg(&erow[wid]);
    int   c = __ldg(&ecol[wid]);
    float v = __ldg(&eval[wid]);

    const float4* x4 = reinterpret_cast<const float4*>(g_x1) + (size_t)c * (N1 / 4);
    float4 a = __ldg(&x4[lane]);        // low  (cols 0..127)
    float4 b = __ldg(&x4[32 + lane]);   // high (cols 128..255)

    red_add_v4(g_sl + (size_t)r * HDIM + lane * 4, v * a.x, v * a.y, v * a.z, v * a.w);
    red_add_v4(g_sh + (size_t)r * HDIM + lane * 4, v * b.x, v * b.y, v * b.z, v * b.w);
}

// ---------------------------------------------------------------------------
// SpMM layer 2: lanes 0-15 -> low half of g_y, lanes 16-31 -> high half
// ---------------------------------------------------------------------------
__global__ void spmm2_kernel(const int* __restrict__ erow,
                             const int* __restrict__ ecol,
                             const float* __restrict__ eval) {
    int wid  = (blockIdx.x * blockDim.x + threadIdx.x) >> 5;
    int lane = threadIdx.x & 31;
    if (wid >= NEDGE) return;
    int   r = __ldg(&erow[wid]);
    int   c = __ldg(&ecol[wid]);
    float v = __ldg(&eval[wid]);

    int half = lane >> 4;
    int l16  = lane & 15;

    float4 a = __ldg(reinterpret_cast<const float4*>(g_y)
                     + (size_t)c * (N2 / 4) + half * 16 + l16);
    float* dst = (half ? g_th : g_tl) + (size_t)r * CDIM + l16 * 4;
    red_add_v4(dst, v * a.x, v * a.y, v * a.z, v * a.w);
}

// ---------------------------------------------------------------------------
// Attention + combine, layer 1: one warp per node (128 feats = float4/lane)
// ---------------------------------------------------------------------------
__global__ void attn1_kernel(const float* __restrict__ a_low,
                             const float* __restrict__ a_high,
                             const float* __restrict__ a_mlp,
                             const float* __restrict__ av) {
    int wid  = (blockIdx.x * blockDim.x + threadIdx.x) >> 5;
    int lane = threadIdx.x & 31;
    if (wid >= NNODES) return;
    size_t base  = (size_t)wid * 32 + lane;        // float4 idx into 128-wide
    size_t xbase = (size_t)wid * (N1 / 4);         // float4 idx into g_x1 row

    float4 sl = reinterpret_cast<const float4*>(g_sl)[base];
    float4 xh = reinterpret_cast<const float4*>(g_x1)[xbase + 32 + lane];
    float4 sh = reinterpret_cast<const float4*>(g_sh)[base];
    float4 xm = reinterpret_cast<const float4*>(g_x1)[xbase + 64 + lane];

    float4 ol, oh, om;
    ol.x = fmaxf(sl.x, 0.f); ol.y = fmaxf(sl.y, 0.f); ol.z = fmaxf(sl.z, 0.f); ol.w = fmaxf(sl.w, 0.f);
    oh.x = fmaxf(xh.x - sh.x, 0.f); oh.y = fmaxf(xh.y - sh.y, 0.f);
    oh.z = fmaxf(xh.z - sh.z, 0.f); oh.w = fmaxf(xh.w - sh.w, 0.f);
    om.x = fmaxf(xm.x, 0.f); om.y = fmaxf(xm.y, 0.f); om.z = fmaxf(xm.z, 0.f); om.w = fmaxf(xm.w, 0.f);

    float4 wl = reinterpret_cast<const float4*>(a_low)[lane];
    float4 wh = reinterpret_cast<const float4*>(a_high)[lane];
    float4 wm = reinterpret_cast<const float4*>(a_mlp)[lane];

    float dl = warpSum(ol.x*wl.x + ol.y*wl.y + ol.z*wl.z + ol.w*wl.w);
    float dh = warpSum(oh.x*wh.x + oh.y*wh.y + oh.z*wh.z + oh.w*wh.w);
    float dm = warpSum(om.x*wm.x + om.y*wm.y + om.z*wm.z + om.w*wm.w);

    float s0 = 1.f / (1.f + expf(-dl));
    float s1 = 1.f / (1.f + expf(-dh));
    float s2 = 1.f / (1.f + expf(-dm));

    const float invT = 1.f / 3.f;
    float l0 = (s0*av[0] + s1*av[3] + s2*av[6]) * invT;
    float l1 = (s0*av[1] + s1*av[4] + s2*av[7]) * invT;
    float l2 = (s0*av[2] + s1*av[5] + s2*av[8]) * invT;
    float mx = fmaxf(l0, fmaxf(l1, l2));
    float e0 = expf(l0 - mx), e1 = expf(l1 - mx), e2 = expf(l2 - mx);
    float inv = 3.f / (e0 + e1 + e2);      // fold *3 here
    float al_ = e0 * inv, ah_ = e1 * inv, am_ = e2 * inv;

    float4 o;
    o.x = al_*ol.x + ah_*oh.x + am_*om.x;
    o.y = al_*ol.y + ah_*oh.y + am_*om.y;
    o.z = al_*ol.z + ah_*oh.z + am_*om.z;
    o.w = al_*ol.w + ah_*oh.w + am_*om.w;
    reinterpret_cast<float4*>(g_h1)[base] = o;
}

// ---------------------------------------------------------------------------
// Attention + combine + log_softmax, layer 2: one warp/node (64 = float2/lane)
// ---------------------------------------------------------------------------
__global__ void attn2_kernel(const float* __restrict__ a_low,
                             const float* __restrict__ a_high,
                             const float* __restrict__ a_mlp,
                             const float* __restrict__ av,
                             float* __restrict__ out) {
    int wid  = (blockIdx.x * blockDim.x + threadIdx.x) >> 5;
    int lane = threadIdx.x & 31;
    if (wid >= NNODES) return;
    size_t base  = (size_t)wid * 32 + lane;    // float2 idx into 64-wide
    size_t ybase = (size_t)wid * (N2 / 2);     // float2 idx into g_y row

    float2 tl = reinterpret_cast<const float2*>(g_tl)[base];
    float2 yh = reinterpret_cast<const float2*>(g_y)[ybase + 32 + lane];
    float2 th = reinterpret_cast<const float2*>(g_th)[base];
    float2 ym = reinterpret_cast<const float2*>(g_y)[ybase + 64 + lane];

    float2 ol, oh, om;
    ol.x = fmaxf(tl.x, 0.f);        ol.y = fmaxf(tl.y, 0.f);
    oh.x = fmaxf(yh.x - th.x, 0.f); oh.y = fmaxf(yh.y - th.y, 0.f);
    om.x = fmaxf(ym.x, 0.f);        om.y = fmaxf(ym.y, 0.f);

    float2 wl = reinterpret_cast<const float2*>(a_low)[lane];
    float2 wh = reinterpret_cast<const float2*>(a_high)[lane];
    float2 wm = reinterpret_cast<const float2*>(a_mlp)[lane];

    float dl = warpSum(ol.x*wl.x + ol.y*wl.y);
    float dh = warpSum(oh.x*wh.x + oh.y*wh.y);
    float dm = warpSum(om.x*wm.x + om.y*wm.y);

    float s0 = 1.f / (1.f + expf(-dl));
    float s1 = 1.f / (1.f + expf(-dh));
    float s2 = 1.f / (1.f + expf(-dm));

    const float invT = 1.f / 3.f;
    float l0 = (s0*av[0] + s1*av[3] + s2*av[6]) * invT;
    float l1 = (s0*av[1] + s1*av[4] + s2*av[7]) * invT;
    float l2 = (s0*av[2] + s1*av[5] + s2*av[8]) * invT;
    float mx = fmaxf(l0, fmaxf(l1, l2));
    float e0 = expf(l0 - mx), e1 = expf(l1 - mx), e2 = expf(l2 - mx);
    float inv = 3.f / (e0 + e1 + e2);
    float al_ = e0 * inv, ah_ = e1 * inv, am_ = e2 * inv;

    float v0 = al_*ol.x + ah_*oh.x + am_*om.x;
    float v1 = al_*ol.y + ah_*oh.y + am_*om.y;

    float rmax = warpMax(fmaxf(v0, v1));
    float sexp = warpSum(expf(v0 - rmax) + expf(v1 - rmax));
    float lse  = rmax + logf(sexp);

    reinterpret_cast<float2*>(out)[base] = make_float2(v0 - lse, v1 - lse);
}

// ---------------------------------------------------------------------------
// Launch
// ---------------------------------------------------------------------------
extern "C" void kernel_launch(void* const* d_in, const int* in_sizes, int n_in,
                              void* d_out, int out_size) {
    const float* x    = (const float*)d_in[0];
    const int*   erow = (const int*)  d_in[1];
    const int*   ecol = (const int*)  d_in[2];
    const float* eval = (const float*)d_in[3];
    const float* W_l  = (const float*)d_in[4];
    const float* W_h  = (const float*)d_in[5];
    const float* W_m  = (const float*)d_in[6];
    const float* a_l  = (const float*)d_in[7];
    const float* a_h  = (const float*)d_in[8];
    const float* a_m  = (const float*)d_in[9];
    const float* av   = (const float*)d_in[10];
    const float* W_l2 = (const float*)d_in[11];
    const float* W_h2 = (const float*)d_in[12];
    const float* W_m2 = (const float*)d_in[13];
    const float* a_l2 = (const float*)d_in[14];
    const float* a_h2 = (const float*)d_in[15];
    const float* a_m2 = (const float*)d_in[16];
    const float* av2  = (const float*)d_in[17];
    float* out = (float*)d_out;

    float *x1, *sl, *sh, *h1, *y, *tl, *th, *w1, *w2;
    cudaGetSymbolAddress((void**)&x1, g_x1);
    cudaGetSymbolAddress((void**)&sl, g_sl);
    cudaGetSymbolAddress((void**)&sh, g_sh);
    cudaGetSymbolAddress((void**)&h1, g_h1);
    cudaGetSymbolAddress((void**)&y,  g_y);
    cudaGetSymbolAddress((void**)&tl, g_tl);
    cudaGetSymbolAddress((void**)&th, g_th);
    cudaGetSymbolAddress((void**)&w1, g_W1);
    cudaGetSymbolAddress((void**)&w2, g_W2);

    // Pack weights + zero accumulators
    pack_w1_kernel<<<(FIN * HDIM + 255) / 256, 256>>>(W_l, W_h, W_m);
    pack_w2_kernel<<<(HDIM * CDIM + 255) / 256, 256>>>(W_l2, W_h2, W_m2);
    cudaMemsetAsync(sl, 0, (size_t)NNODES * HDIM * sizeof(float));
    cudaMemsetAsync(sh, 0, (size_t)NNODES * HDIM * sizeof(float));
    cudaMemsetAsync(tl, 0, (size_t)NNODES * CDIM * sizeof(float));
    cudaMemsetAsync(th, 0, (size_t)NNODES * CDIM * sizeof(float));

    // Layer 1 fused GEMM: [50000,512] @ [512,384]
    {
        dim3 grid(N1 / 128, (NNODES + 127) / 128);
        gemm3_tf32_kernel<128, 128, 32, 32, 64><<<grid, 256>>>(x, w1, x1, NNODES, N1, FIN);
    }

    int eb = (NEDGE * 32 + 255) / 256;
    int nb = (NNODES * 32 + 255) / 256;
    spmm1_kernel<<<eb, 256>>>(erow, ecol, eval);
    attn1_kernel<<<nb, 256>>>(a_l, a_h, a_m, av);

    // Layer 2 fused GEMM: [50000,128] @ [128,192]
    {
        dim3 grid(N2 / 64, (NNODES + 127) / 128);
        gemm3_tf32_kernel<128, 64, 32, 32, 32><<<grid, 256>>>(h1, w2, y, NNODES, N2, HDIM);
    }

    spmm2_kernel<<<eb, 256>>>(erow, ecol, eval);
    attn2_kernel<<<nb, 256>>>(a_l2, a_h2, a_m2, av2, out);
}

// round 4
// speedup vs baseline: 2.0537x; 1.2815x over previous
#include <cuda_runtime.h>
#include <math.h>
#include <stdint.h>

#define NNODES 50000
#define FIN    512
#define HDIM   128
#define CDIM   64
#define NEDGE  800000
#define N1     384     // fused layer-1 width: [low | high | mlp] * 128
#define N2     192     // fused layer-2 width: [low | high | mlp] * 64

// ---------------------------------------------------------------------------
// Scratch (no allocations allowed -> __device__ globals)
// ---------------------------------------------------------------------------
__device__ float g_x1[NNODES * N1];     // X @ [W_l|W_h|W_m]
__device__ float g_h1[NNODES * HDIM];   // layer-1 output
__device__ float g_y [NNODES * N2];     // h1 @ [W_l2|W_h2|W_m2]
__device__ float g_W1[FIN * N1];        // packed layer-1 weights
__device__ float g_W2[HDIM * N2];       // packed layer-2 weights
// CSR build
__device__ int   g_cnt[NNODES];
__device__ int   g_off[NNODES];
__device__ int   g_cur[NNODES];
__device__ int   g_bsum[256];
__device__ int   g_scol[NEDGE];
__device__ float g_sval[NEDGE];

// ---------------------------------------------------------------------------
// Utilities
// ---------------------------------------------------------------------------
__device__ __forceinline__ float warpSum(float v) {
    #pragma unroll
    for (int o = 16; o > 0; o >>= 1) v += __shfl_xor_sync(0xFFFFFFFFu, v, o);
    return v;
}
__device__ __forceinline__ float warpMax(float v) {
    #pragma unroll
    for (int o = 16; o > 0; o >>= 1) v = fmaxf(v, __shfl_xor_sync(0xFFFFFFFFu, v, o));
    return v;
}

// tf32 hi/lo split: hi keeps the top 10 mantissa bits (exact tf32), lo = v - hi.
__device__ __forceinline__ void split_tf32(float v, uint32_t& hi, uint32_t& lo) {
    uint32_t h = __float_as_uint(v) & 0xFFFFE000u;
    hi = h;
    lo = __float_as_uint(v - __uint_as_float(h));
}

__device__ __forceinline__ void mma_tf32(float* d, const uint32_t* a, const uint32_t* b) {
    asm volatile(
        "mma.sync.aligned.m16n8k8.row.col.f32.tf32.tf32.f32 "
        "{%0,%1,%2,%3}, {%4,%5,%6,%7}, {%8,%9}, {%0,%1,%2,%3};\n"
        : "+f"(d[0]), "+f"(d[1]), "+f"(d[2]), "+f"(d[3])
        : "r"(a[0]), "r"(a[1]), "r"(a[2]), "r"(a[3]), "r"(b[0]), "r"(b[1]));
}

// ---------------------------------------------------------------------------
// Weight packing
// ---------------------------------------------------------------------------
__global__ void pack_w1_kernel(const float* __restrict__ wl,
                               const float* __restrict__ wh,
                               const float* __restrict__ wm) {
    int i = blockIdx.x * blockDim.x + threadIdx.x;
    if (i >= FIN * HDIM) return;
    int k = i / HDIM, j = i % HDIM;
    g_W1[k * N1 + j]            = wl[i];
    g_W1[k * N1 + HDIM + j]     = wh[i];
    g_W1[k * N1 + 2 * HDIM + j] = wm[i];
}
__global__ void pack_w2_kernel(const float* __restrict__ wl,
                               const float* __restrict__ wh,
                               const float* __restrict__ wm) {
    int i = blockIdx.x * blockDim.x + threadIdx.x;
    if (i >= HDIM * CDIM) return;
    int k = i / CDIM, j = i % CDIM;
    g_W2[k * N2 + j]            = wl[i];
    g_W2[k * N2 + CDIM + j]     = wh[i];
    g_W2[k * N2 + 2 * CDIM + j] = wm[i];
}

// ---------------------------------------------------------------------------
// CSR build: histogram -> 2-level exclusive scan -> scatter
// ---------------------------------------------------------------------------
__global__ void hist_kernel(const int* __restrict__ erow) {
    int e = blockIdx.x * blockDim.x + threadIdx.x;
    if (e < NEDGE) atomicAdd(&g_cnt[erow[e]], 1);
}

__global__ void scan1_kernel() {   // grid: ceil(NNODES/256), block: 256
    __shared__ int s[256];
    int tid = threadIdx.x;
    int gi  = blockIdx.x * 256 + tid;
    int v   = (gi < NNODES) ? g_cnt[gi] : 0;
    s[tid] = v;
    __syncthreads();
    #pragma unroll
    for (int o = 1; o < 256; o <<= 1) {
        int t = (tid >= o) ? s[tid - o] : 0;
        __syncthreads();
        s[tid] += t;
        __syncthreads();
    }
    if (gi < NNODES) g_off[gi] = s[tid] - v;       // exclusive within block
    if (tid == 255)  g_bsum[blockIdx.x] = s[255];  // block total
}

__global__ void scan2_kernel(int nb) {  // 1 block, 256 threads (nb <= 256)
    __shared__ int s[256];
    int tid = threadIdx.x;
    int v   = (tid < nb) ? g_bsum[tid] : 0;
    s[tid] = v;
    __syncthreads();
    #pragma unroll
    for (int o = 1; o < 256; o <<= 1) {
        int t = (tid >= o) ? s[tid - o] : 0;
        __syncthreads();
        s[tid] += t;
        __syncthreads();
    }
    if (tid < nb) g_bsum[tid] = s[tid] - v;        // exclusive block offsets
}

__global__ void scan3_kernel() {
    int gi = blockIdx.x * blockDim.x + threadIdx.x;
    if (gi >= NNODES) return;
    int o = g_off[gi] + g_bsum[gi >> 8];
    g_off[gi] = o;
    g_cur[gi] = o;
}

__global__ void scatter_kernel(const int* __restrict__ erow,
                               const int* __restrict__ ecol,
                               const float* __restrict__ eval) {
    int e = blockIdx.x * blockDim.x + threadIdx.x;
    if (e >= NEDGE) return;
    int r = erow[e];
    int p = atomicAdd(&g_cur[r], 1);
    g_scol[p] = ecol[e];
    g_sval[p] = eval[e];
}

// ---------------------------------------------------------------------------
// TF32 3x-split tensor-core GEMM:  C[M,N] = A[M,K] @ B[K,N]  (row-major)
// ---------------------------------------------------------------------------
template<int BM, int BN, int BK, int WM, int WN>
__global__ __launch_bounds__(256)
void gemm3_tf32_kernel(const float* __restrict__ A,
                       const float* __restrict__ B,
                       float* __restrict__ C,
                       int M, int N, int K) {
    constexpr int WARPS_N = BN / WN;
    constexpr int MT = WM / 16;
    constexpr int NT = WN / 8;

    __shared__ float As[BK][BM + 4];
    __shared__ float Bs[BK][BN + 4];

    const int tid  = threadIdx.x;
    const int warp = tid >> 5;
    const int lane = tid & 31;
    const int g    = lane >> 2;
    const int t    = lane & 3;
    const int wmB  = (warp / WARPS_N) * WM;
    const int wnB  = (warp % WARPS_N) * WN;
    const int bm   = blockIdx.y * BM;
    const int bn   = blockIdx.x * BN;

    float acc[MT][NT][4];
    #pragma unroll
    for (int i = 0; i < MT; i++)
        #pragma unroll
        for (int j = 0; j < NT; j++)
            #pragma unroll
            for (int q = 0; q < 4; q++) acc[i][j][q] = 0.f;

    for (int k0 = 0; k0 < K; k0 += BK) {
        #pragma unroll
        for (int idx = tid * 4; idx < BM * BK; idx += 256 * 4) {
            int r = idx / BK;
            int c = idx % BK;
            int gr = bm + r;
            float4 v = make_float4(0.f, 0.f, 0.f, 0.f);
            if (gr < M)
                v = *reinterpret_cast<const float4*>(&A[(size_t)gr * K + k0 + c]);
            As[c + 0][r] = v.x;
            As[c + 1][r] = v.y;
            As[c + 2][r] = v.z;
            As[c + 3][r] = v.w;
        }
        #pragma unroll
        for (int idx = tid * 4; idx < BK * BN; idx += 256 * 4) {
            int r = idx / BN;
            int c = idx % BN;
            *reinterpret_cast<float4*>(&Bs[r][c]) =
                *reinterpret_cast<const float4*>(&B[(size_t)(k0 + r) * N + bn + c]);
        }
        __syncthreads();

        #pragma unroll
        for (int kk = 0; kk < BK; kk += 8) {
            uint32_t ah[MT][4], al[MT][4];
            #pragma unroll
            for (int mt = 0; mt < MT; mt++) {
                int mb = wmB + mt * 16;
                split_tf32(As[kk + t]    [mb + g],     ah[mt][0], al[mt][0]);
                split_tf32(As[kk + t]    [mb + g + 8], ah[mt][1], al[mt][1]);
                split_tf32(As[kk + t + 4][mb + g],     ah[mt][2], al[mt][2]);
                split_tf32(As[kk + t + 4][mb + g + 8], ah[mt][3], al[mt][3]);
            }
            #pragma unroll
            for (int nt = 0; nt < NT; nt++) {
                uint32_t bh[2], bl[2];
                int nb = wnB + nt * 8 + g;
                split_tf32(Bs[kk + t]    [nb], bh[0], bl[0]);
                split_tf32(Bs[kk + t + 4][nb], bh[1], bl[1]);
                #pragma unroll
                for (int mt = 0; mt < MT; mt++) {
                    mma_tf32(acc[mt][nt], al[mt], bh);
                    mma_tf32(acc[mt][nt], ah[mt], bl);
                    mma_tf32(acc[mt][nt], ah[mt], bh);
                }
            }
        }
        __syncthreads();
    }

    #pragma unroll
    for (int mt = 0; mt < MT; mt++) {
        int r0 = bm + wmB + mt * 16 + g;
        int r1 = r0 + 8;
        #pragma unroll
        for (int nt = 0; nt < NT; nt++) {
            int c0 = bn + wnB + nt * 8 + 2 * t;
            if (r0 < M) {
                float2 v = make_float2(acc[mt][nt][0], acc[mt][nt][1]);
                *reinterpret_cast<float2*>(&C[(size_t)r0 * N + c0]) = v;
            }
            if (r1 < M) {
                float2 v = make_float2(acc[mt][nt][2], acc[mt][nt][3]);
                *reinterpret_cast<float2*>(&C[(size_t)r1 * N + c0]) = v;
            }
        }
    }
}

// ---------------------------------------------------------------------------
// Fused SpMM + attention, layer 1: one warp per row, register accumulation
// ---------------------------------------------------------------------------
__global__ __launch_bounds__(256)
void spmm_attn1_kernel(const float* __restrict__ a_low,
                       const float* __restrict__ a_high,
                       const float* __restrict__ a_mlp,
                       const float* __restrict__ av) {
    int row  = (blockIdx.x * blockDim.x + threadIdx.x) >> 5;
    int lane = threadIdx.x & 31;
    if (row >= NNODES) return;

    int start = g_off[row];
    int deg   = g_cnt[row];

    float4 accl = make_float4(0.f, 0.f, 0.f, 0.f);
    float4 acch = make_float4(0.f, 0.f, 0.f, 0.f);

    for (int base = 0; base < deg; base += 32) {
        int n = min(32, deg - base);
        int   c = 0;
        float v = 0.f;
        if (lane < n) {
            c = g_scol[start + base + lane];
            v = g_sval[start + base + lane];
        }
        for (int j = 0; j < n; j++) {
            int   cj = __shfl_sync(0xFFFFFFFFu, c, j);
            float vj = __shfl_sync(0xFFFFFFFFu, v, j);
            const float4* p = reinterpret_cast<const float4*>(g_x1) + (size_t)cj * (N1 / 4);
            float4 a = __ldg(&p[lane]);        // low  (cols 0..127)
            float4 b = __ldg(&p[32 + lane]);   // high (cols 128..255)
            accl.x += vj * a.x; accl.y += vj * a.y; accl.z += vj * a.z; accl.w += vj * a.w;
            acch.x += vj * b.x; acch.y += vj * b.y; acch.z += vj * b.z; acch.w += vj * b.w;
        }
    }

    const float4* pr = reinterpret_cast<const float4*>(g_x1) + (size_t)row * (N1 / 4);
    float4 xh = pr[32 + lane];
    float4 xm = pr[64 + lane];

    float4 ol, oh, om;
    ol.x = fmaxf(accl.x, 0.f); ol.y = fmaxf(accl.y, 0.f);
    ol.z = fmaxf(accl.z, 0.f); ol.w = fmaxf(accl.w, 0.f);
    oh.x = fmaxf(xh.x - acch.x, 0.f); oh.y = fmaxf(xh.y - acch.y, 0.f);
    oh.z = fmaxf(xh.z - acch.z, 0.f); oh.w = fmaxf(xh.w - acch.w, 0.f);
    om.x = fmaxf(xm.x, 0.f); om.y = fmaxf(xm.y, 0.f);
    om.z = fmaxf(xm.z, 0.f); om.w = fmaxf(xm.w, 0.f);

    float4 wl = reinterpret_cast<const float4*>(a_low)[lane];
    float4 wh = reinterpret_cast<const float4*>(a_high)[lane];
    float4 wm = reinterpret_cast<const float4*>(a_mlp)[lane];

    float dl = warpSum(ol.x*wl.x + ol.y*wl.y + ol.z*wl.z + ol.w*wl.w);
    float dh = warpSum(oh.x*wh.x + oh.y*wh.y + oh.z*wh.z + oh.w*wh.w);
    float dm = warpSum(om.x*wm.x + om.y*wm.y + om.z*wm.z + om.w*wm.w);

    float s0 = 1.f / (1.f + expf(-dl));
    float s1 = 1.f / (1.f + expf(-dh));
    float s2 = 1.f / (1.f + expf(-dm));

    const float invT = 1.f / 3.f;
    float l0 = (s0*av[0] + s1*av[3] + s2*av[6]) * invT;
    float l1 = (s0*av[1] + s1*av[4] + s2*av[7]) * invT;
    float l2 = (s0*av[2] + s1*av[5] + s2*av[8]) * invT;
    float mx = fmaxf(l0, fmaxf(l1, l2));
    float e0 = expf(l0 - mx), e1 = expf(l1 - mx), e2 = expf(l2 - mx);
    float inv = 3.f / (e0 + e1 + e2);      // fold *3 here
    float al_ = e0 * inv, ah_ = e1 * inv, am_ = e2 * inv;

    float4 o;
    o.x = al_*ol.x + ah_*oh.x + am_*om.x;
    o.y = al_*ol.y + ah_*oh.y + am_*om.y;
    o.z = al_*ol.z + ah_*oh.z + am_*om.z;
    o.w = al_*ol.w + ah_*oh.w + am_*om.w;
    reinterpret_cast<float4*>(g_h1)[(size_t)row * 32 + lane] = o;
}

// ---------------------------------------------------------------------------
// Fused SpMM + attention + log_softmax, layer 2: one warp per row (float2/lane)
// ---------------------------------------------------------------------------
__global__ __launch_bounds__(256)
void spmm_attn2_kernel(const float* __restrict__ a_low,
                       const float* __restrict__ a_high,
                       const float* __restrict__ a_mlp,
                       const float* __restrict__ av,
                       float* __restrict__ out) {
    int row  = (blockIdx.x * blockDim.x + threadIdx.x) >> 5;
    int lane = threadIdx.x & 31;
    if (row >= NNODES) return;

    int start = g_off[row];
    int deg   = g_cnt[row];

    float2 accl = make_float2(0.f, 0.f);
    float2 acch = make_float2(0.f, 0.f);

    for (int base = 0; base < deg; base += 32) {
        int n = min(32, deg - base);
        int   c = 0;
        float v = 0.f;
        if (lane < n) {
            c = g_scol[start + base + lane];
            v = g_sval[start + base + lane];
        }
        for (int j = 0; j < n; j++) {
            int   cj = __shfl_sync(0xFFFFFFFFu, c, j);
            float vj = __shfl_sync(0xFFFFFFFFu, v, j);
            const float* rp = g_y + (size_t)cj * N2;
            float2 a = __ldg(reinterpret_cast<const float2*>(rp) + lane);          // low
            float2 b = __ldg(reinterpret_cast<const float2*>(rp + CDIM) + lane);   // high
            accl.x += vj * a.x; accl.y += vj * a.y;
            acch.x += vj * b.x; acch.y += vj * b.y;
        }
    }

    const float* rr = g_y + (size_t)row * N2;
    float2 yh = reinterpret_cast<const float2*>(rr + CDIM)[lane];
    float2 ym = reinterpret_cast<const float2*>(rr + 2 * CDIM)[lane];

    float2 ol, oh, om;
    ol.x = fmaxf(accl.x, 0.f);        ol.y = fmaxf(accl.y, 0.f);
    oh.x = fmaxf(yh.x - acch.x, 0.f); oh.y = fmaxf(yh.y - acch.y, 0.f);
    om.x = fmaxf(ym.x, 0.f);          om.y = fmaxf(ym.y, 0.f);

    float2 wl = reinterpret_cast<const float2*>(a_low)[lane];
    float2 wh = reinterpret_cast<const float2*>(a_high)[lane];
    float2 wm = reinterpret_cast<const float2*>(a_mlp)[lane];

    float dl = warpSum(ol.x*wl.x + ol.y*wl.y);
    float dh = warpSum(oh.x*wh.x + oh.y*wh.y);
    float dm = warpSum(om.x*wm.x + om.y*wm.y);

    float s0 = 1.f / (1.f + expf(-dl));
    float s1 = 1.f / (1.f + expf(-dh));
    float s2 = 1.f / (1.f + expf(-dm));

    const float invT = 1.f / 3.f;
    float l0 = (s0*av[0] + s1*av[3] + s2*av[6]) * invT;
    float l1 = (s0*av[1] + s1*av[4] + s2*av[7]) * invT;
    float l2 = (s0*av[2] + s1*av[5] + s2*av[8]) * invT;
    float mx = fmaxf(l0, fmaxf(l1, l2));
    float e0 = expf(l0 - mx), e1 = expf(l1 - mx), e2 = expf(l2 - mx);
    float inv = 3.f / (e0 + e1 + e2);
    float al_ = e0 * inv, ah_ = e1 * inv, am_ = e2 * inv;

    float v0 = al_*ol.x + ah_*oh.x + am_*om.x;
    float v1 = al_*ol.y + ah_*oh.y + am_*om.y;

    float rmax = warpMax(fmaxf(v0, v1));
    float sexp = warpSum(expf(v0 - rmax) + expf(v1 - rmax));
    float lse  = rmax + logf(sexp);

    reinterpret_cast<float2*>(out)[(size_t)row * 32 + lane] = make_float2(v0 - lse, v1 - lse);
}

// ---------------------------------------------------------------------------
// Launch
// ---------------------------------------------------------------------------
extern "C" void kernel_launch(void* const* d_in, const int* in_sizes, int n_in,
                              void* d_out, int out_size) {
    const float* x    = (const float*)d_in[0];
    const int*   erow = (const int*)  d_in[1];
    const int*   ecol = (const int*)  d_in[2];
    const float* eval = (const float*)d_in[3];
    const float* W_l  = (const float*)d_in[4];
    const float* W_h  = (const float*)d_in[5];
    const float* W_m  = (const float*)d_in[6];
    const float* a_l  = (const float*)d_in[7];
    const float* a_h  = (const float*)d_in[8];
    const float* a_m  = (const float*)d_in[9];
    const float* av   = (const float*)d_in[10];
    const float* W_l2 = (const float*)d_in[11];
    const float* W_h2 = (const float*)d_in[12];
    const float* W_m2 = (const float*)d_in[13];
    const float* a_l2 = (const float*)d_in[14];
    const float* a_h2 = (const float*)d_in[15];
    const float* a_m2 = (const float*)d_in[16];
    const float* av2  = (const float*)d_in[17];
    float* out = (float*)d_out;

    float *x1, *h1, *y, *w1, *w2;
    int *cnt;
    cudaGetSymbolAddress((void**)&x1,  g_x1);
    cudaGetSymbolAddress((void**)&h1,  g_h1);
    cudaGetSymbolAddress((void**)&y,   g_y);
    cudaGetSymbolAddress((void**)&w1,  g_W1);
    cudaGetSymbolAddress((void**)&w2,  g_W2);
    cudaGetSymbolAddress((void**)&cnt, g_cnt);

    const int SCAN_BLOCKS = (NNODES + 255) / 256;   // 196

    // Weight packing + CSR build
    pack_w1_kernel<<<(FIN * HDIM + 255) / 256, 256>>>(W_l, W_h, W_m);
    pack_w2_kernel<<<(HDIM * CDIM + 255) / 256, 256>>>(W_l2, W_h2, W_m2);
    cudaMemsetAsync(cnt, 0, NNODES * sizeof(int));
    hist_kernel<<<(NEDGE + 255) / 256, 256>>>(erow);
    scan1_kernel<<<SCAN_BLOCKS, 256>>>();
    scan2_kernel<<<1, 256>>>(SCAN_BLOCKS);
    scan3_kernel<<<SCAN_BLOCKS, 256>>>();
    scatter_kernel<<<(NEDGE + 255) / 256, 256>>>(erow, ecol, eval);

    // Layer 1 fused GEMM: [50000,512] @ [512,384]
    {
        dim3 grid(N1 / 128, (NNODES + 127) / 128);
        gemm3_tf32_kernel<128, 128, 32, 32, 64><<<grid, 256>>>(x, w1, x1, NNODES, N1, FIN);
    }

    int nb = (NNODES * 32 + 255) / 256;
    spmm_attn1_kernel<<<nb, 256>>>(a_l, a_h, a_m, av);

    // Layer 2 fused GEMM: [50000,128] @ [128,192]
    {
        dim3 grid(N2 / 64, (NNODES + 127) / 128);
        gemm3_tf32_kernel<128, 64, 32, 32, 32><<<grid, 256>>>(h1, w2, y, NNODES, N2, HDIM);
    }

    spmm_attn2_kernel<<<nb, 256>>>(a_l2, a_h2, a_m2, av2, out);
}